// round 12
// baseline (speedup 1.0000x reference)
#include <cuda_runtime.h>
#include <cuda_bf16.h>

#define R_EARTH  6371000.0f
#define DEG2RADF 0.017453292519943295f
#define DT_SEC   600.0f
#define NSTEPS   48

#define WOUT 28           // output columns per warp (32 lanes - 2*2 halo)
#define SH   64           // rows per strip
#define WPB  8            // warps per block

// Scratch ping-pong buffer (B*H*W = 8*1024*1024 floats = 32 MB) — static device
// global, NOT an allocation.
__device__ __align__(16) float g_scratch[8u * 1024u * 1024u];

// Per-row reciprocal dx terms (H <= 4096) + dy scalars.
__device__ float g_inv_dx[4096];
__device__ float g_inv_2dx[4096];
__device__ float g_inv_dy;
__device__ float g_inv_2dy;

__global__ void setup_kernel(const float* __restrict__ lat,
                             const float* __restrict__ lon, int H) {
    float dlat = lat[1] - lat[0];
    float dlon = lon[1] - lon[0];
    float dy = R_EARTH * DEG2RADF * dlat;
    if (blockIdx.x == 0 && threadIdx.x == 0) {
        g_inv_dy  = 1.0f / dy;
        g_inv_2dy = 0.5f / dy;
    }
    float dx0 = R_EARTH * DEG2RADF * dlon;
    for (int i = blockIdx.x * blockDim.x + threadIdx.x; i < H;
         i += gridDim.x * blockDim.x) {
        float dx = dx0 * cosf(lat[i] * DEG2RADF);
        g_inv_dx[i]  = 1.0f / dx;
        g_inv_2dx[i] = 0.5f / dx;
    }
}

// One fused timestep, register-rolling sweep version.
// Each warp: 28 output columns x SH rows. Lane l covers x = wc*28 + l - 2.
// Rolling registers carry T rows (r-1,r,r+1), horizontal binomial sums of the
// advected field (hs at rows r-1,r,r+1), and mask rows. No shared memory.
__global__ __launch_bounds__(256)
void step_kernel(const float* __restrict__ src_ext, int src_is_scratch,
                 float* __restrict__ dst_ext, int dst_is_scratch,
                 const float* __restrict__ ug, const float* __restrict__ vg,
                 const float* __restrict__ mask, int H, int W,
                 int NXW, int NYS, int total_warps) {
    const float* __restrict__ src = src_is_scratch ? g_scratch : src_ext;
    float* __restrict__       dst = dst_is_scratch ? g_scratch : dst_ext;

    const int lane = threadIdx.x & 31;
    const int wu   = blockIdx.x * WPB + (threadIdx.x >> 5);
    if (wu >= total_warps) return;

    const int wc = wu % NXW;
    const int ys = (wu / NXW) % NYS;
    const int b  = wu / (NXW * NYS);

    const int x    = wc * WOUT + lane - 2;
    const int xc   = x < 0 ? 0 : (x >= W ? W - 1 : x);
    const bool in_x = (x >= 0) && (x < W);
    const bool store_lane = in_x && (lane >= 2) && (lane <= 29);

    const int y0 = ys * SH;
    const int y1 = min(y0 + SH, H);

    const int plane = H * W;
    const float* __restrict__ Tb  = src  + b * plane + xc;
    const float* __restrict__ ugb = ug   + b * plane + xc;
    const float* __restrict__ vgb = vg   + b * plane + xc;
    const float* __restrict__ mb  = mask + xc;
    float* __restrict__ dstb = dst + b * plane + x;

    const float inv_dy  = g_inv_dy;
    const float inv_2dy = g_inv_2dy;
    const bool x_lo = (x == 0);
    const bool x_hi = (x == W - 1);

    // Prologue: T rows y0-2 and y0-1 (clamped addresses; values at
    // out-of-domain rows are never consumed).
    int yA = y0 - 2; yA = yA < 0 ? 0 : yA;
    int yB = y0 - 1; yB = yB < 0 ? 0 : yB;
    float t_m1 = Tb[yA * W];
    float t_0  = Tb[yB * W];
    float hs_m1 = 0.0f, hs_0 = 0.0f;
    float m_prev = 0.0f;

    for (int r = y0 - 1; r <= y1; ++r) {
        // Load T[r+1] (clamped row).
        int yn = r + 1; yn = yn < 0 ? 0 : (yn >= H ? H - 1 : yn);
        float t_p1 = Tb[yn * W];

        // Advected field A at row r (0 outside domain => conv zero padding).
        float a = 0.0f;
        float m_cur = 0.0f;
        if (r >= 0 && r < H) {                       // warp-uniform branch
            const int ro = r * W;
            float ugv = ugb[ro];
            float vgv = vgb[ro];
            m_cur = mb[ro];
            float dTdy;
            if (r == 0)           dTdy = (t_p1 - t_0) * inv_dy;
            else if (r == H - 1)  dTdy = (t_0 - t_m1) * inv_dy;
            else                  dTdy = (t_p1 - t_m1) * inv_2dy;
            float tl = __shfl_up_sync(0xffffffffu, t_0, 1);
            float tr = __shfl_down_sync(0xffffffffu, t_0, 1);
            float dTdx;
            if (x_lo)       dTdx = (tr - t_0) * g_inv_dx[r];
            else if (x_hi)  dTdx = (t_0 - tl) * g_inv_dx[r];
            else            dTdx = (tr - tl) * g_inv_2dx[r];
            float adv = fmaf(ugv, dTdx, vgv * dTdy);
            a = fmaf(-DT_SEC * m_cur, adv, t_0);
            if (!in_x) a = 0.0f;                     // zero pad at x edges
        }

        // Horizontal binomial of A (valid at lanes 1..30; consumed 2..29).
        float al = __shfl_up_sync(0xffffffffu, a, 1);
        float ar = __shfl_down_sync(0xffffffffu, a, 1);
        float hs_p1 = al + 2.0f * a + ar;

        // Output row o = r - 1 (vertical binomial of hs), masked.
        if (r >= y0 + 1) {
            float v = (hs_m1 + 2.0f * hs_0 + hs_p1) * 0.0625f * m_prev;
            if (store_lane) dstb[(r - 1) * W] = v;
        }

        t_m1 = t_0;  t_0 = t_p1;
        hs_m1 = hs_0; hs_0 = hs_p1;
        m_prev = m_cur;
    }
}

extern "C" void kernel_launch(void* const* d_in, const int* in_sizes, int n_in,
                              void* d_out, int out_size) {
    const float* T    = (const float*)d_in[0];
    const float* ug   = (const float*)d_in[1];
    const float* vg   = (const float*)d_in[2];
    const float* lat  = (const float*)d_in[3];
    const float* lon  = (const float*)d_in[4];
    const float* mask = (const float*)d_in[5];
    float* out = (float*)d_out;

    const int H = in_sizes[3];
    const int W = in_sizes[4];
    const int B = in_sizes[0] / (H * W);

    setup_kernel<<<(H + 255) / 256, 256>>>(lat, lon, H);

    const int NXW = (W + WOUT - 1) / WOUT;
    const int NYS = (H + SH - 1) / SH;
    const int total_warps = B * NYS * NXW;
    const int blocks = (total_warps + WPB - 1) / WPB;

    // Ping-pong so that the final step (s = NSTEPS-1) writes d_out.
    for (int s = 0; s < NSTEPS; s++) {
        int dst_is_out = ((NSTEPS - 1 - s) % 2) == 0;   // last step -> out
        int src_is_scratch, dst_is_scratch;
        const float* src_ext;
        float* dst_ext;
        if (s == 0) { src_ext = T; src_is_scratch = 0; }
        else {
            int prev_dst_is_out = ((NSTEPS - s) % 2) == 0;
            if (prev_dst_is_out) { src_ext = out; src_is_scratch = 0; }
            else                 { src_ext = nullptr; src_is_scratch = 1; }
        }
        if (dst_is_out) { dst_ext = out; dst_is_scratch = 0; }
        else            { dst_ext = nullptr; dst_is_scratch = 1; }

        step_kernel<<<blocks, 256>>>(src_ext, src_is_scratch,
                                     dst_ext, dst_is_scratch,
                                     ug, vg, mask, H, W,
                                     NXW, NYS, total_warps);
    }
}

// round 13
// speedup vs baseline: 1.7745x; 1.7745x over previous
#include <cuda_runtime.h>
#include <cuda_bf16.h>

#define R_EARTH  6371000.0f
#define DEG2RADF 0.017453292519943295f
#define DT_SEC   600.0f
#define NSTEPS   48

#define WOUT 28           // output columns per warp (32 lanes - 2*2 halo)
#define SH   64           // rows per strip (output rows), multiple of 4
#define WPB  8            // warps per block

// Scratch ping-pong buffer (B*H*W = 8*1024*1024 floats = 32 MB) — static device
// global, NOT an allocation.
__device__ __align__(16) float g_scratch[8u * 1024u * 1024u];

// Per-row reciprocal dx terms (H <= 4096) + dy scalars.
__device__ float g_inv_dx[4096];
__device__ float g_inv_2dx[4096];
__device__ float g_inv_dy;
__device__ float g_inv_2dy;

__global__ void setup_kernel(const float* __restrict__ lat,
                             const float* __restrict__ lon, int H) {
    float dlat = lat[1] - lat[0];
    float dlon = lon[1] - lon[0];
    float dy = R_EARTH * DEG2RADF * dlat;
    if (blockIdx.x == 0 && threadIdx.x == 0) {
        g_inv_dy  = 1.0f / dy;
        g_inv_2dy = 0.5f / dy;
    }
    float dx0 = R_EARTH * DEG2RADF * dlon;
    for (int i = blockIdx.x * blockDim.x + threadIdx.x; i < H;
         i += gridDim.x * blockDim.x) {
        float dx = dx0 * cosf(lat[i] * DEG2RADF);
        g_inv_dx[i]  = 1.0f / dx;
        g_inv_2dx[i] = 0.5f / dx;
    }
}

// One fused timestep, register-rolling sweep, 4-row software pipeline.
// Each warp: 28 output columns x SH rows. Lane l covers x = wc*28 + l - 2.
__global__ __launch_bounds__(256, 4)
void step_kernel(const float* __restrict__ src_ext, int src_is_scratch,
                 float* __restrict__ dst_ext, int dst_is_scratch,
                 const float* __restrict__ ug, const float* __restrict__ vg,
                 const float* __restrict__ mask, int H, int W,
                 int NXW, int NYS, int total_warps) {
    const float* __restrict__ src = src_is_scratch ? g_scratch : src_ext;
    float* __restrict__       dst = dst_is_scratch ? g_scratch : dst_ext;

    const int lane = threadIdx.x & 31;
    const int wu   = blockIdx.x * WPB + (threadIdx.x >> 5);
    if (wu >= total_warps) return;

    const int wc = wu % NXW;
    const int ys = (wu / NXW) % NYS;
    const int b  = wu / (NXW * NYS);

    const int x    = wc * WOUT + lane - 2;
    const int xc   = x < 0 ? 0 : (x >= W ? W - 1 : x);
    const bool in_x = (x >= 0) && (x < W);
    const bool store_lane = in_x && (lane >= 2) && (lane <= 29);

    const int y0 = ys * SH;
    const int y1 = min(y0 + SH, H);

    const int plane = H * W;
    const float* __restrict__ Tb  = src  + b * plane + xc;
    const float* __restrict__ ugb = ug   + b * plane + xc;
    const float* __restrict__ vgb = vg   + b * plane + xc;
    const float* __restrict__ mb  = mask + xc;
    float* __restrict__ dstb = dst + b * plane + x;

    const float inv_dy  = g_inv_dy;
    const float inv_2dy = g_inv_2dy;
    const bool x_lo = (x == 0);
    const bool x_hi = (x == W - 1);

    // ---- Prologue: rows r = y0-1, y0 (generic scalar path, no store) ----
    int yA = y0 - 2; yA = yA < 0 ? 0 : yA;
    int yB = y0 - 1; yB = yB < 0 ? 0 : yB;
    float t_m1 = Tb[yA * W];
    float t_0  = Tb[yB * W];
    float hs_m1 = 0.0f, hs_0 = 0.0f;
    float m_roll = 0.0f;

    #pragma unroll
    for (int p = 0; p < 2; ++p) {
        int r = y0 - 1 + p;
        int yn = r + 1; yn = yn < 0 ? 0 : (yn >= H ? H - 1 : yn);
        float t_p1 = Tb[yn * W];
        float a = 0.0f, m_cur = 0.0f;
        if (r >= 0 && r < H) {                      // warp-uniform
            const int ro = r * W;
            float ugv = ugb[ro];
            float vgv = vgb[ro];
            m_cur = mb[ro];
            float dTdy;
            if (r == 0)           dTdy = (t_p1 - t_0) * inv_dy;
            else if (r == H - 1)  dTdy = (t_0 - t_m1) * inv_dy;
            else                  dTdy = (t_p1 - t_m1) * inv_2dy;
            float tl = __shfl_up_sync(0xffffffffu, t_0, 1);
            float tr = __shfl_down_sync(0xffffffffu, t_0, 1);
            float dTdx;
            if (x_lo)       dTdx = (tr - t_0) * g_inv_dx[r];
            else if (x_hi)  dTdx = (t_0 - tl) * g_inv_dx[r];
            else            dTdx = (tr - tl) * g_inv_2dx[r];
            float adv = fmaf(ugv, dTdx, vgv * dTdy);
            a = fmaf(-DT_SEC * m_cur, adv, t_0);
            if (!in_x) a = 0.0f;
        }
        float al = __shfl_up_sync(0xffffffffu, a, 1);
        float ar = __shfl_down_sync(0xffffffffu, a, 1);
        float hs_p1 = al + 2.0f * a + ar;
        t_m1 = t_0;  t_0 = t_p1;
        hs_m1 = hs_0; hs_0 = hs_p1;
        m_roll = m_cur;
    }
    // Now: t_m1=T[y0], t_0=T[y0+1], hs_m1=hs[y0-1], hs_0=hs[y0], m_roll=m[y0].

    // ---- Main loop: chunks of 4 output rows, batched loads (MLP=16) ----
    for (int ob = y0; ob < y1; ob += 4) {
        float tp[4], ugv[4], vgv[4], mv[4];
        #pragma unroll
        for (int j = 0; j < 4; ++j) {
            int r  = ob + 1 + j;                    // advection row
            int rt = r + 1;  rt = rt >= H ? H - 1 : rt;   // T row to load
            int rc = r >= H ? H - 1 : r;            // clamped uv/mask row
            tp[j]  = Tb[rt * W];
            ugv[j] = ugb[rc * W];
            vgv[j] = vgb[rc * W];
            mv[j]  = mb[rc * W];
        }
        #pragma unroll
        for (int j = 0; j < 4; ++j) {
            int r = ob + 1 + j;
            float t_p1 = tp[j];
            float a = 0.0f, m_cur = 0.0f;
            if (r < H) {                            // warp-uniform
                m_cur = mv[j];
                float dTdy = (r == H - 1) ? (t_0 - t_m1) * inv_dy
                                          : (t_p1 - t_m1) * inv_2dy;
                float tl = __shfl_up_sync(0xffffffffu, t_0, 1);
                float tr = __shfl_down_sync(0xffffffffu, t_0, 1);
                float dTdx;
                if (x_lo)       dTdx = (tr - t_0) * g_inv_dx[r];
                else if (x_hi)  dTdx = (t_0 - tl) * g_inv_dx[r];
                else            dTdx = (tr - tl) * g_inv_2dx[r];
                float adv = fmaf(ugv[j], dTdx, vgv[j] * dTdy);
                a = fmaf(-DT_SEC * m_cur, adv, t_0);
                if (!in_x) a = 0.0f;
            }
            float al = __shfl_up_sync(0xffffffffu, a, 1);
            float ar = __shfl_down_sync(0xffffffffu, a, 1);
            float hs_p1 = al + 2.0f * a + ar;

            // Output row o = r - 1 = ob + j
            float v = (hs_m1 + 2.0f * hs_0 + hs_p1) * 0.0625f * m_roll;
            if (store_lane) dstb[(r - 1) * W] = v;

            t_m1 = t_0;  t_0 = t_p1;
            hs_m1 = hs_0; hs_0 = hs_p1;
            m_roll = m_cur;
        }
    }
}

extern "C" void kernel_launch(void* const* d_in, const int* in_sizes, int n_in,
                              void* d_out, int out_size) {
    const float* T    = (const float*)d_in[0];
    const float* ug   = (const float*)d_in[1];
    const float* vg   = (const float*)d_in[2];
    const float* lat  = (const float*)d_in[3];
    const float* lon  = (const float*)d_in[4];
    const float* mask = (const float*)d_in[5];
    float* out = (float*)d_out;

    const int H = in_sizes[3];
    const int W = in_sizes[4];
    const int B = in_sizes[0] / (H * W);

    setup_kernel<<<(H + 255) / 256, 256>>>(lat, lon, H);

    const int NXW = (W + WOUT - 1) / WOUT;
    const int NYS = (H + SH - 1) / SH;
    const int total_warps = B * NYS * NXW;
    const int blocks = (total_warps + WPB - 1) / WPB;

    // Ping-pong so that the final step (s = NSTEPS-1) writes d_out.
    for (int s = 0; s < NSTEPS; s++) {
        int dst_is_out = ((NSTEPS - 1 - s) % 2) == 0;   // last step -> out
        int src_is_scratch, dst_is_scratch;
        const float* src_ext;
        float* dst_ext;
        if (s == 0) { src_ext = T; src_is_scratch = 0; }
        else {
            int prev_dst_is_out = ((NSTEPS - s) % 2) == 0;
            if (prev_dst_is_out) { src_ext = out; src_is_scratch = 0; }
            else                 { src_ext = nullptr; src_is_scratch = 1; }
        }
        if (dst_is_out) { dst_ext = out; dst_is_scratch = 0; }
        else            { dst_ext = nullptr; dst_is_scratch = 1; }

        step_kernel<<<blocks, 256>>>(src_ext, src_is_scratch,
                                     dst_ext, dst_is_scratch,
                                     ug, vg, mask, H, W,
                                     NXW, NYS, total_warps);
    }
}